// round 16
// baseline (speedup 1.0000x reference)
#include <cuda_runtime.h>
#include <cuda_bf16.h>
#include <math.h>

// ---------------------------------------------------------------------------
// Problem constants
// ---------------------------------------------------------------------------
#define BATCH   4096
#define NTOK    64
#define CDIM    96
#define NHEADS  3
#define HD      32
#define K4      384
#define MTOK    (BATCH * NTOK)               // 262144 tokens
#define SCALE   0.17677669529663687f

// ---------------------------------------------------------------------------
// Scratch (device globals)
// ---------------------------------------------------------------------------
__device__ __nv_bfloat16 g_Xs_hi[(size_t)MTOK * CDIM];
__device__ __nv_bfloat16 g_Xs_lo[(size_t)MTOK * CDIM];
__device__ __nv_bfloat16 g_Xe_hi[(size_t)MTOK * CDIM];
__device__ __nv_bfloat16 g_Xe_lo[(size_t)MTOK * CDIM];
__device__ __nv_bfloat16 g_Ws_hi[K4 * CDIM];
__device__ __nv_bfloat16 g_Ws_lo[K4 * CDIM];
__device__ __nv_bfloat16 g_We_hi[K4 * CDIM];
__device__ __nv_bfloat16 g_We_lo[K4 * CDIM];
__device__ __nv_bfloat16 g_Wpv_hi[CDIM * 2 * CDIM];   // [96][192] row-major
__device__ __nv_bfloat16 g_Wpv_lo[CDIM * 2 * CDIM];
__device__ __nv_bfloat16 g_Wph_hi[CDIM * 2 * CDIM];
__device__ __nv_bfloat16 g_Wph_lo[CDIM * 2 * CDIM];
// Stage-1 output: projections as bf16 hi/lo, row-major [token][384]
__device__ __nv_bfloat16 g_Ys_hi[(size_t)MTOK * K4];
__device__ __nv_bfloat16 g_Ys_lo[(size_t)MTOK * K4];
__device__ __nv_bfloat16 g_Ye_hi[(size_t)MTOK * K4];
__device__ __nv_bfloat16 g_Ye_lo[(size_t)MTOK * K4];
// Attention merges, ROW-MAJOR bf16 hi/lo: Mv = [cv | sv], Mh = [ch | sh]
__device__ __nv_bfloat16 g_Mv_hi[(size_t)MTOK * 2 * CDIM];
__device__ __nv_bfloat16 g_Mv_lo[(size_t)MTOK * 2 * CDIM];
__device__ __nv_bfloat16 g_Mh_hi[(size_t)MTOK * 2 * CDIM];
__device__ __nv_bfloat16 g_Mh_lo[(size_t)MTOK * 2 * CDIM];
__device__ float g_bias[4 * NHEADS * NTOK * NTOK];    // [tbl][h][i*64+j]

typedef unsigned long long u64;

__device__ __forceinline__ float fast_exp(float x)
{
    const float L2E   = 1.4426950408889634f;
    const float MAGIC = 12582912.0f;
    float y = x * L2E;
    float t = y + MAGIC;
    float f = y - (t - MAGIC);
    int   i = __float_as_int(t) - 0x4B400000;
    float p = 1.33335581e-3f;
    p = fmaf(p, f, 9.61804886e-3f);
    p = fmaf(p, f, 5.55041087e-2f);
    p = fmaf(p, f, 2.40226507e-1f);
    p = fmaf(p, f, 6.93147182e-1f);
    p = fmaf(p, f, 1.0f);
    return __int_as_float(__float_as_int(p) + (i << 23));
}

// split two floats into bf16x2 hi-pack and lo-pack
__device__ __forceinline__ void split2(float a, float b, unsigned& hp, unsigned& lp)
{
    __nv_bfloat16 ha = __float2bfloat16(a);
    __nv_bfloat16 hb = __float2bfloat16(b);
    __nv_bfloat162 hh; hh.x = ha; hh.y = hb;
    __nv_bfloat162 ll;
    ll.x = __float2bfloat16(a - __bfloat162float(ha));
    ll.y = __float2bfloat16(b - __bfloat162float(hb));
    hp = *(unsigned*)&hh;
    lp = *(unsigned*)&ll;
}

// ---------------------------------------------------------------------------
// cp.async helpers
// ---------------------------------------------------------------------------
__device__ __forceinline__ void cpa16(unsigned dst, const void* src)
{
    asm volatile("cp.async.ca.shared.global [%0], [%1], 16;"
                 :: "r"(dst), "l"(src));
}
__device__ __forceinline__ void cpa_commit()
{
    asm volatile("cp.async.commit_group;");
}

// ---------------------------------------------------------------------------
// mma.sync / ldmatrix (baseline sm_80 PTX — compiles under sm_103 target)
// ---------------------------------------------------------------------------
__device__ __forceinline__ void ldsm4(unsigned* r, unsigned addr)
{
    asm volatile("ldmatrix.sync.aligned.m8n8.x4.shared.b16 {%0,%1,%2,%3}, [%4];"
                 : "=r"(r[0]), "=r"(r[1]), "=r"(r[2]), "=r"(r[3]) : "r"(addr));
}
__device__ __forceinline__ void ldsm4t(unsigned* r, unsigned addr)
{
    asm volatile("ldmatrix.sync.aligned.m8n8.x4.trans.shared.b16 {%0,%1,%2,%3}, [%4];"
                 : "=r"(r[0]), "=r"(r[1]), "=r"(r[2]), "=r"(r[3]) : "r"(addr));
}
__device__ __forceinline__ void mma16816(float* d, const unsigned* a,
                                         unsigned b0, unsigned b1)
{
    asm volatile(
        "mma.sync.aligned.m16n8k16.row.col.f32.bf16.bf16.f32 "
        "{%0,%1,%2,%3}, {%4,%5,%6,%7}, {%8,%9}, {%0,%1,%2,%3};"
        : "+f"(d[0]), "+f"(d[1]), "+f"(d[2]), "+f"(d[3])
        : "r"(a[0]), "r"(a[1]), "r"(a[2]), "r"(a[3]), "r"(b0), "r"(b1));
}

// ---------------------------------------------------------------------------
// Prepass kernels
// ---------------------------------------------------------------------------
__global__ void bias_gather(const float* __restrict__ tcv,
                            const float* __restrict__ tsv,
                            const float* __restrict__ tch,
                            const float* __restrict__ tsh,
                            const int*   __restrict__ rel_idx)
{
    const int tbl = blockIdx.y;
    const int h   = blockIdx.z;
    const float* T = (tbl == 0) ? tcv : (tbl == 1) ? tsv : (tbl == 2) ? tch : tsh;
    int idx = blockIdx.x * 256 + threadIdx.x;      // idx = i*64 + j
    g_bias[(size_t)(tbl * NHEADS + h) * (NTOK * NTOK) + idx] =
        T[rel_idx[idx] * NHEADS + h];
}

__global__ __launch_bounds__(256)
void convert_split(const float* __restrict__ X,
                   __nv_bfloat16* __restrict__ hi,
                   __nv_bfloat16* __restrict__ lo, size_t n)
{
    size_t idx = ((size_t)blockIdx.x * 256 + threadIdx.x) * 4;
    if (idx >= n) return;
    float4 v = *(const float4*)(X + idx);
    float xs[4] = {v.x, v.y, v.z, v.w};
    __nv_bfloat16 h4[4], l4[4];
    #pragma unroll
    for (int c = 0; c < 4; c++) {
        __nv_bfloat16 hb = __float2bfloat16(xs[c]);
        h4[c] = hb;
        l4[c] = __float2bfloat16(xs[c] - __bfloat162float(hb));
    }
    *(ulonglong1*)(hi + idx) = *(ulonglong1*)h4;
    *(ulonglong1*)(lo + idx) = *(ulonglong1*)l4;
}

// ---------------------------------------------------------------------------
// Stage-1 tensor GEMM (HMMA): Y = X @ W^T + b, bf16 2-term compensated.
// Output written as bf16 hi/lo row-major (attention consumes it directly).
// ---------------------------------------------------------------------------
#define PB 104
#define MATB (128 * PB * 2)
#define MMA_SMEM (4 * MATB)

__global__ __launch_bounds__(256)
void mma_gemm(const __nv_bfloat16* __restrict__ XsH,
              const __nv_bfloat16* __restrict__ XsL,
              const __nv_bfloat16* __restrict__ XeH,
              const __nv_bfloat16* __restrict__ XeL,
              const __nv_bfloat16* __restrict__ WsH,
              const __nv_bfloat16* __restrict__ WsL,
              const __nv_bfloat16* __restrict__ WeH,
              const __nv_bfloat16* __restrict__ WeL,
              const float* __restrict__ bs, const float* __restrict__ be)
{
    extern __shared__ char smc[];
    const unsigned sb = (unsigned)__cvta_generic_to_shared(smc);

    const int t    = threadIdx.x;
    const int lane = t & 31;
    const int wid  = t >> 5;
    const int mBase = blockIdx.x * 128;
    const int nBase = blockIdx.y * 128;
    const int z     = blockIdx.z;

    const __nv_bfloat16* Ah = z ? XeH : XsH;
    const __nv_bfloat16* Al = z ? XeL : XsL;
    const __nv_bfloat16* Bh = z ? WeH : WsH;
    const __nv_bfloat16* Bl = z ? WeL : WsL;
    const float* bias = z ? be : bs;
    __nv_bfloat16* Yh = z ? g_Ye_hi : g_Ys_hi;
    __nv_bfloat16* Yl = z ? g_Ye_lo : g_Ys_lo;

    {
        const __nv_bfloat16* srcs[4] = {
            Ah + (size_t)mBase * CDIM, Al + (size_t)mBase * CDIM,
            Bh + (size_t)nBase * CDIM, Bl + (size_t)nBase * CDIM };
        #pragma unroll
        for (int m = 0; m < 4; m++) {
            const __nv_bfloat16* src = srcs[m];
            unsigned dst = sb + m * MATB;
            #pragma unroll
            for (int it = 0; it < 6; it++) {
                int g   = t + 256 * it;
                int row = g / 12;
                int gr  = g % 12;
                cpa16(dst + row * (PB * 2) + gr * 16, src + row * CDIM + gr * 8);
            }
        }
        cpa_commit();
        asm volatile("cp.async.wait_group 0;");
    }
    __syncthreads();

    const int mW = (wid & 3) * 32;
    const int nW = (wid >> 2) * 64;

    float D[16][4];
    #pragma unroll
    for (int i = 0; i < 16; i++)
        #pragma unroll
        for (int j = 0; j < 4; j++) D[i][j] = 0.f;

    const unsigned frow = (unsigned)(lane & 15);
    const unsigned fkof = (unsigned)(lane >> 4) * 8;

    #pragma unroll
    for (int s = 0; s < 6; s++) {
        const unsigned k0 = s * 16;
        unsigned ah[2][4], al[2][4];
        #pragma unroll
        for (int m = 0; m < 2; m++) {
            unsigned off = ((mW + m * 16 + frow) * PB + k0 + fkof) * 2;
            ldsm4(ah[m], sb + off);
            ldsm4(al[m], sb + MATB + off);
        }
        #pragma unroll
        for (int p = 0; p < 4; p++) {
            unsigned boff = ((nW + p * 16 + frow) * PB + k0 + fkof) * 2;
            unsigned bh[4], bl[4];
            ldsm4(bh, sb + 2 * MATB + boff);
            ldsm4(bl, sb + 3 * MATB + boff);
            #pragma unroll
            for (int m = 0; m < 2; m++) {
                #pragma unroll
                for (int na = 0; na < 2; na++) {
                    float* d = D[m * 8 + p * 2 + na];
                    mma16816(d, ah[m], bh[na], bh[na + 2]);
                    mma16816(d, ah[m], bl[na], bl[na + 2]);
                    mma16816(d, al[m], bh[na], bh[na + 2]);
                }
            }
        }
    }

    // ---- epilogue: bias + bf16 hi/lo stores ----
    #pragma unroll
    for (int m = 0; m < 2; m++) {
        int rA = mBase + mW + m * 16 + (lane >> 2);
        #pragma unroll
        for (int n = 0; n < 8; n++) {
            int col = nBase + nW + n * 8 + (lane & 3) * 2;
            float2 bv = *(const float2*)&bias[col];
            float* d = D[m * 8 + n];
            unsigned h0, l0, h1, l1;
            split2(d[0] + bv.x, d[1] + bv.y, h0, l0);
            split2(d[2] + bv.x, d[3] + bv.y, h1, l1);
            size_t o0 = (size_t)rA * K4 + col;
            size_t o1 = (size_t)(rA + 8) * K4 + col;
            *(unsigned*)&Yh[o0] = h0;
            *(unsigned*)&Yl[o0] = l0;
            *(unsigned*)&Yh[o1] = h1;
            *(unsigned*)&Yl[o1] = l1;
        }
    }
}

// ---------------------------------------------------------------------------
// Window attention on HMMA. Grid (BATCH, NHEADS, 2); block 256 (8 warps).
// warps 0-3 = type A (16 query rows each), warps 4-7 = type B.
// All tiles arrive pre-split bf16 hi/lo via cp.async (no in-kernel convert).
// Q/K/V all row-major [token][32 dims], pitch 40 halves (80 B = 5x16B).
// PV uses ldmatrix.trans on row-major V.
// ---------------------------------------------------------------------------
#define TQ 2560                               // halves per tile-half (64*40)
#define ATT_HALVES (8 * TQ)                   // 40960 B
// tile-half order: 0=K_hi 1=K_lo 2=V_hi 3=V_lo 4=QA_hi 5=QA_lo 6=QB_hi 7=QB_lo

__global__ __launch_bounds__(256)
void attn_mma()
{
    __shared__ __nv_bfloat16 smh[ATT_HALVES];
    const unsigned sb = (unsigned)__cvta_generic_to_shared(smh);

    const int b = blockIdx.x;
    const int h = blockIdx.y;
    const int z = blockIdx.z;
    const __nv_bfloat16* __restrict__ Yhi = z ? g_Ye_hi : g_Ys_hi;
    const __nv_bfloat16* __restrict__ Ylo = z ? g_Ye_lo : g_Ys_lo;

    const int t    = threadIdx.x;
    const int lane = t & 31;
    const int wid  = t >> 5;

    // ---- cp.async fill: 8 tile-halves x 64 rows x 4 granules(16B) ----
    {
        const int colOff[4] = {0, CDIM, 2 * CDIM, 3 * CDIM};   // K,V,QA,QB
        const int row = t >> 2;
        const int gr  = t & 3;
        const size_t srcRow = (size_t)(b * NTOK + row) * K4 + h * HD + gr * 8;
        #pragma unroll
        for (int th = 0; th < 8; th++) {
            const __nv_bfloat16* src =
                ((th & 1) ? Ylo : Yhi) + srcRow + colOff[th >> 1];
            cpa16(sb + (th * TQ + row * 40 + gr * 8) * 2, src);
        }
        cpa_commit();
        asm volatile("cp.async.wait_group 0;");
    }
    __syncthreads();

    const int type    = wid >> 2;
    const int rowBase = (wid & 3) * 16;
    const float scl   = type ? (z ? SCALE : SCALE * SCALE)
                             : (z ? 1.0f  : SCALE);
    const int  tbl    = type ? (z ? 2 : 3) : (z ? 1 : 0);
    const float* bias = g_bias + (size_t)(tbl * NHEADS + h) * (NTOK * NTOK);

    const unsigned frow = (unsigned)(lane & 15);
    const unsigned fkof = (unsigned)(lane >> 4) * 8;
    const int g = lane >> 2;
    const int q = lane & 3;

    // ---- Q fragments (hi/lo, 2 k-steps) ----
    const unsigned qbase = (type ? 6 : 4) * TQ;
    unsigned qh[2][4], ql[2][4];
    #pragma unroll
    for (int ks = 0; ks < 2; ks++) {
        unsigned a = sb + (qbase + (rowBase + frow) * 40 + ks * 16 + fkof) * 2;
        ldsm4(qh[ks], a);
        ldsm4(ql[ks], a + TQ * 2);
    }

    // ---- QK^T: D[8 n-tiles][4] ----
    float D[8][4];
    #pragma unroll
    for (int i = 0; i < 8; i++)
        #pragma unroll
        for (int j = 0; j < 4; j++) D[i][j] = 0.f;

    #pragma unroll
    for (int ng = 0; ng < 4; ng++) {
        unsigned kh[2][4], kl[2][4];
        #pragma unroll
        for (int ks = 0; ks < 2; ks++) {
            unsigned a = sb + ((ng * 16 + frow) * 40 + ks * 16 + fkof) * 2;
            ldsm4(kh[ks], a);
            ldsm4(kl[ks], a + TQ * 2);
        }
        #pragma unroll
        for (int ks = 0; ks < 2; ks++) {
            #pragma unroll
            for (int na = 0; na < 2; na++) {
                float* d = D[2 * ng + na];
                mma16816(d, qh[ks], kh[ks][na], kh[ks][na + 2]);
                mma16816(d, qh[ks], kl[ks][na], kl[ks][na + 2]);
                mma16816(d, ql[ks], kh[ks][na], kh[ks][na + 2]);
            }
        }
    }

    // ---- scale + bias ----
    #pragma unroll
    for (int nt = 0; nt < 8; nt++) {
        float2 b0 = *(const float2*)&bias[(rowBase + g) * NTOK + nt * 8 + 2 * q];
        float2 b1 = *(const float2*)&bias[(rowBase + g + 8) * NTOK + nt * 8 + 2 * q];
        D[nt][0] = fmaf(scl, D[nt][0], b0.x);
        D[nt][1] = fmaf(scl, D[nt][1], b0.y);
        D[nt][2] = fmaf(scl, D[nt][2], b1.x);
        D[nt][3] = fmaf(scl, D[nt][3], b1.y);
    }

    // ---- row softmax (quad shuffles; rows g and g+8) ----
    float m0 = -1e30f, m1 = -1e30f;
    #pragma unroll
    for (int nt = 0; nt < 8; nt++) {
        m0 = fmaxf(m0, fmaxf(D[nt][0], D[nt][1]));
        m1 = fmaxf(m1, fmaxf(D[nt][2], D[nt][3]));
    }
    m0 = fmaxf(m0, __shfl_xor_sync(0xffffffffu, m0, 1));
    m0 = fmaxf(m0, __shfl_xor_sync(0xffffffffu, m0, 2));
    m1 = fmaxf(m1, __shfl_xor_sync(0xffffffffu, m1, 1));
    m1 = fmaxf(m1, __shfl_xor_sync(0xffffffffu, m1, 2));

    float s0 = 0.f, s1 = 0.f;
    #pragma unroll
    for (int nt = 0; nt < 8; nt++) {
        D[nt][0] = fast_exp(D[nt][0] - m0);
        D[nt][1] = fast_exp(D[nt][1] - m0);
        D[nt][2] = fast_exp(D[nt][2] - m1);
        D[nt][3] = fast_exp(D[nt][3] - m1);
        s0 += D[nt][0] + D[nt][1];
        s1 += D[nt][2] + D[nt][3];
    }
    s0 += __shfl_xor_sync(0xffffffffu, s0, 1);
    s0 += __shfl_xor_sync(0xffffffffu, s0, 2);
    s1 += __shfl_xor_sync(0xffffffffu, s1, 1);
    s1 += __shfl_xor_sync(0xffffffffu, s1, 2);
    const float i0 = 1.f / s0;
    const float i1 = 1.f / s1;

    // ---- P fragments (hi/lo) from D registers; inv folded in ----
    unsigned pah[4][4], pal[4][4];
    #pragma unroll
    for (int kt = 0; kt < 4; kt++) {
        #pragma unroll
        for (int half = 0; half < 2; half++) {       // n-tile 2kt, 2kt+1
            float c0 = D[2 * kt + half][0] * i0;
            float c1 = D[2 * kt + half][1] * i0;
            float c2 = D[2 * kt + half][2] * i1;
            float c3 = D[2 * kt + half][3] * i1;
            split2(c0, c1, pah[kt][2 * half + 0], pal[kt][2 * half + 0]);
            split2(c2, c3, pah[kt][2 * half + 1], pal[kt][2 * half + 1]);
        }
    }

    // ---- PV: O[4 n-tiles][4]; V row-major, trans-ldmatrix B fragments ----
    float O[4][4];
    #pragma unroll
    for (int i = 0; i < 4; i++)
        #pragma unroll
        for (int j = 0; j < 4; j++) O[i][j] = 0.f;

    #pragma unroll
    for (int nv = 0; nv < 2; nv++) {
        #pragma unroll
        for (int kt = 0; kt < 4; kt++) {
            unsigned a = sb + (2 * TQ + (kt * 16 + frow) * 40 + nv * 16 + fkof) * 2;
            unsigned vh[4], vl[4];
            ldsm4t(vh, a);
            ldsm4t(vl, a + TQ * 2);
            #pragma unroll
            for (int na = 0; na < 2; na++) {
                float* d = O[2 * nv + na];
                mma16816(d, pah[kt], vh[2 * na], vh[2 * na + 1]);
                mma16816(d, pah[kt], vl[2 * na], vl[2 * na + 1]);
                mma16816(d, pal[kt], vh[2 * na], vh[2 * na + 1]);
            }
        }
    }

    // ---- epilogue: bf16 hi/lo row-major stores into merge buffers ----
    __nv_bfloat16* oHi = type ? g_Mh_hi : g_Mv_hi;
    __nv_bfloat16* oLo = type ? g_Mh_lo : g_Mv_lo;
    const int colb = (type ? (z ? 0 : CDIM) : (z ? CDIM : 0)) + h * HD;

    #pragma unroll
    for (int nt = 0; nt < 4; nt++) {
        int col = colb + nt * 8 + 2 * q;
        #pragma unroll
        for (int half = 0; half < 2; half++) {
            int row = b * NTOK + rowBase + g + 8 * half;
            unsigned hp, lp;
            split2(O[nt][2 * half + 0], O[nt][2 * half + 1], hp, lp);
            *(unsigned*)&oHi[(size_t)row * (2 * CDIM) + col] = hp;
            *(unsigned*)&oLo[(size_t)row * (2 * CDIM) + col] = lp;
        }
    }
}

// ---------------------------------------------------------------------------
// Stage-3 tensor GEMM (HMMA): C[M,96] = M[token,192] @ W[96,192]^T + bias.
// ---------------------------------------------------------------------------
#define PB2   200
#define AROW2 (PB2 * 2)
#define S3_AH 0
#define S3_AL (128 * AROW2)
#define S3_BH (2 * 128 * AROW2)
#define S3_BL (S3_BH + CDIM * AROW2)
#define S3_SMEM (S3_BL + CDIM * AROW2)

__global__ __launch_bounds__(256)
void mma_gemm3(const float* __restrict__ bpv, const float* __restrict__ bph,
               float* __restrict__ out, float* __restrict__ state)
{
    extern __shared__ char smc[];
    const unsigned sb = (unsigned)__cvta_generic_to_shared(smc);

    const int t    = threadIdx.x;
    const int lane = t & 31;
    const int wid  = t >> 5;
    const int mBase = blockIdx.x * 128;
    const int z     = blockIdx.z;

    const __nv_bfloat16* Ah = z ? g_Mh_hi : g_Mv_hi;
    const __nv_bfloat16* Al = z ? g_Mh_lo : g_Mv_lo;
    const __nv_bfloat16* Bh = z ? g_Wph_hi : g_Wpv_hi;
    const __nv_bfloat16* Bl = z ? g_Wph_lo : g_Wpv_lo;
    const float* bias = z ? bph : bpv;
    float* C = z ? state : out;

    {
        const __nv_bfloat16* aH = Ah + (size_t)mBase * (2 * CDIM);
        const __nv_bfloat16* aL = Al + (size_t)mBase * (2 * CDIM);
        #pragma unroll
        for (int it = 0; it < 12; it++) {
            int g   = t + 256 * it;
            int row = g / 24;
            int gr  = g % 24;
            cpa16(sb + S3_AH + row * AROW2 + gr * 16, aH + row * (2 * CDIM) + gr * 8);
            cpa16(sb + S3_AL + row * AROW2 + gr * 16, aL + row * (2 * CDIM) + gr * 8);
        }
        #pragma unroll
        for (int it = 0; it < 9; it++) {
            int g = t + 256 * it;
            int row = g / 24;
            int gr  = g % 24;
            cpa16(sb + S3_BH + row * AROW2 + gr * 16, Bh + row * (2 * CDIM) + gr * 8);
            cpa16(sb + S3_BL + row * AROW2 + gr * 16, Bl + row * (2 * CDIM) + gr * 8);
        }
        cpa_commit();
        asm volatile("cp.async.wait_group 0;");
    }
    __syncthreads();

    const int mW = (wid & 3) * 32;
    const int nW = (wid >> 2) * 48;

    float D[12][4];
    #pragma unroll
    for (int i = 0; i < 12; i++)
        #pragma unroll
        for (int j = 0; j < 4; j++) D[i][j] = 0.f;

    const unsigned frow = (unsigned)(lane & 15);
    const unsigned fkof = (unsigned)(lane >> 4) * 8;

    #pragma unroll
    for (int s = 0; s < 12; s++) {
        const unsigned k0 = s * 16;
        unsigned ah[2][4], al[2][4];
        #pragma unroll
        for (int m = 0; m < 2; m++) {
            unsigned off = ((mW + m * 16 + frow) * PB2 + k0 + fkof) * 2;
            ldsm4(ah[m], sb + S3_AH + off);
            ldsm4(al[m], sb + S3_AL + off);
        }
        #pragma unroll
        for (int p = 0; p < 3; p++) {
            unsigned boff = ((nW + p * 16 + frow) * PB2 + k0 + fkof) * 2;
            unsigned bh[4], bl[4];
            ldsm4(bh, sb + S3_BH + boff);
            ldsm4(bl, sb + S3_BL + boff);
            #pragma unroll
            for (int m = 0; m < 2; m++) {
                #pragma unroll
                for (int na = 0; na < 2; na++) {
                    float* d = D[m * 6 + p * 2 + na];
                    mma16816(d, ah[m], bh[na], bh[na + 2]);
                    mma16816(d, ah[m], bl[na], bl[na + 2]);
                    mma16816(d, al[m], bh[na], bh[na + 2]);
                }
            }
        }
    }

    #pragma unroll
    for (int m = 0; m < 2; m++) {
        int rA = mBase + mW + m * 16 + (lane >> 2);
        #pragma unroll
        for (int n = 0; n < 6; n++) {
            int col = nW + n * 8 + (lane & 3) * 2;
            float2 bv = *(const float2*)&bias[col];
            float* d = D[m * 6 + n];
            float2 r0; r0.x = d[0] + bv.x; r0.y = d[1] + bv.y;
            float2 r1; r1.x = d[2] + bv.x; r1.y = d[3] + bv.y;
            *(float2*)&C[(size_t)rA * CDIM + col]       = r0;
            *(float2*)&C[(size_t)(rA + 8) * CDIM + col] = r1;
        }
    }
}

// ---------------------------------------------------------------------------
// Launch
// ---------------------------------------------------------------------------
extern "C" void kernel_launch(void* const* d_in, const int* in_sizes, int n_in,
                              void* d_out, int out_size)
{
    const float* input_x = (const float*)d_in[0];
    const float* state_x = (const float*)d_in[1];
    const float* Ws      = (const float*)d_in[2];
    const float* bs      = (const float*)d_in[3];
    const float* We      = (const float*)d_in[4];
    const float* be      = (const float*)d_in[5];
    const float* tcv     = (const float*)d_in[6];
    const float* tsv     = (const float*)d_in[7];
    const float* tch     = (const float*)d_in[8];
    const float* tsh     = (const float*)d_in[9];
    const float* Wpv     = (const float*)d_in[10];
    const float* bpv     = (const float*)d_in[11];
    const float* Wph     = (const float*)d_in[12];
    const float* bph     = (const float*)d_in[13];
    const int*   rel_idx = (const int*)d_in[14];

    float* out   = (float*)d_out;
    float* state = out + (size_t)MTOK * CDIM;

    __nv_bfloat16 *pXsH, *pXsL, *pXeH, *pXeL, *pWsH, *pWsL, *pWeH, *pWeL;
    __nv_bfloat16 *pWpvH, *pWpvL, *pWphH, *pWphL;
    cudaGetSymbolAddress((void**)&pXsH, g_Xs_hi);
    cudaGetSymbolAddress((void**)&pXsL, g_Xs_lo);
    cudaGetSymbolAddress((void**)&pXeH, g_Xe_hi);
    cudaGetSymbolAddress((void**)&pXeL, g_Xe_lo);
    cudaGetSymbolAddress((void**)&pWsH, g_Ws_hi);
    cudaGetSymbolAddress((void**)&pWsL, g_Ws_lo);
    cudaGetSymbolAddress((void**)&pWeH, g_We_hi);
    cudaGetSymbolAddress((void**)&pWeL, g_We_lo);
    cudaGetSymbolAddress((void**)&pWpvH, g_Wpv_hi);
    cudaGetSymbolAddress((void**)&pWpvL, g_Wpv_lo);
    cudaGetSymbolAddress((void**)&pWphH, g_Wph_hi);
    cudaGetSymbolAddress((void**)&pWphL, g_Wph_lo);

    cudaFuncSetAttribute(mma_gemm,
                         cudaFuncAttributeMaxDynamicSharedMemorySize, MMA_SMEM);
    cudaFuncSetAttribute(mma_gemm3,
                         cudaFuncAttributeMaxDynamicSharedMemorySize, S3_SMEM);

    // Prepass: converts + bias gather
    {
        size_t nX = (size_t)MTOK * CDIM;
        convert_split<<<(unsigned)((nX / 4 + 255) / 256), 256>>>(state_x, pXsH, pXsL, nX);
        convert_split<<<(unsigned)((nX / 4 + 255) / 256), 256>>>(input_x, pXeH, pXeL, nX);
        size_t nW = (size_t)K4 * CDIM;
        convert_split<<<(unsigned)((nW / 4 + 255) / 256), 256>>>(Ws, pWsH, pWsL, nW);
        convert_split<<<(unsigned)((nW / 4 + 255) / 256), 256>>>(We, pWeH, pWeL, nW);
        size_t nP = (size_t)CDIM * 2 * CDIM;
        convert_split<<<(unsigned)((nP / 4 + 255) / 256), 256>>>(Wpv, pWpvH, pWpvL, nP);
        convert_split<<<(unsigned)((nP / 4 + 255) / 256), 256>>>(Wph, pWphH, pWphL, nP);
        dim3 gb(NTOK * NTOK / 256, 4, NHEADS);
        bias_gather<<<gb, 256>>>(tcv, tsv, tch, tsh, rel_idx);
    }

    // Stage 1: projections on HMMA -> bf16 hi/lo Y
    {
        dim3 grid(MTOK / 128, K4 / 128, 2);
        mma_gemm<<<grid, 256, MMA_SMEM>>>(pXsH, pXsL, pXeH, pXeL,
                                          pWsH, pWsL, pWeH, pWeL, bs, be);
    }

    // Stage 2: window attention on HMMA (cp.async tile fill, trans-V)
    {
        dim3 grid(BATCH, NHEADS, 2);
        attn_mma<<<grid, 256>>>();
    }

    // Stage 3: output projections on HMMA
    {
        dim3 grid(MTOK / 128, 1, 2);
        mma_gemm3<<<grid, 256, S3_SMEM>>>(bpv, bph, out, state);
    }
}

// round 17
// speedup vs baseline: 1.0946x; 1.0946x over previous
#include <cuda_runtime.h>
#include <cuda_bf16.h>
#include <math.h>

// ---------------------------------------------------------------------------
// Problem constants
// ---------------------------------------------------------------------------
#define BATCH   4096
#define NTOK    64
#define CDIM    96
#define NHEADS  3
#define HD      32
#define K4      384
#define MTOK    (BATCH * NTOK)               // 262144 tokens
#define SCALE   0.17677669529663687f

// ---------------------------------------------------------------------------
// Scratch (device globals)
// ---------------------------------------------------------------------------
__device__ __nv_bfloat16 g_Ws_hi[K4 * CDIM];
__device__ __nv_bfloat16 g_Ws_lo[K4 * CDIM];
__device__ __nv_bfloat16 g_We_hi[K4 * CDIM];
__device__ __nv_bfloat16 g_We_lo[K4 * CDIM];
__device__ __nv_bfloat16 g_Wpv_hi[CDIM * 2 * CDIM];   // [96][192] row-major
__device__ __nv_bfloat16 g_Wpv_lo[CDIM * 2 * CDIM];
__device__ __nv_bfloat16 g_Wph_hi[CDIM * 2 * CDIM];
__device__ __nv_bfloat16 g_Wph_lo[CDIM * 2 * CDIM];
__device__ float g_Ys [(size_t)MTOK * K4];            // row-major [token][384]
__device__ float g_Ye [(size_t)MTOK * K4];
// Attention merges, ROW-MAJOR bf16 hi/lo: Mv = [cv | sv], Mh = [ch | sh]
__device__ __nv_bfloat16 g_Mv_hi[(size_t)MTOK * 2 * CDIM];
__device__ __nv_bfloat16 g_Mv_lo[(size_t)MTOK * 2 * CDIM];
__device__ __nv_bfloat16 g_Mh_hi[(size_t)MTOK * 2 * CDIM];
__device__ __nv_bfloat16 g_Mh_lo[(size_t)MTOK * 2 * CDIM];
__device__ float g_bias[4 * NHEADS * NTOK * NTOK];    // [tbl][h][i*64+j]

typedef unsigned long long u64;

__device__ __forceinline__ float fast_exp(float x)
{
    const float L2E   = 1.4426950408889634f;
    const float MAGIC = 12582912.0f;
    float y = x * L2E;
    float t = y + MAGIC;
    float f = y - (t - MAGIC);
    int   i = __float_as_int(t) - 0x4B400000;
    float p = 1.33335581e-3f;
    p = fmaf(p, f, 9.61804886e-3f);
    p = fmaf(p, f, 5.55041087e-2f);
    p = fmaf(p, f, 2.40226507e-1f);
    p = fmaf(p, f, 6.93147182e-1f);
    p = fmaf(p, f, 1.0f);
    return __int_as_float(__float_as_int(p) + (i << 23));
}

// split two floats into bf16x2 hi-pack and lo-pack
__device__ __forceinline__ void split2(float a, float b, unsigned& hp, unsigned& lp)
{
    __nv_bfloat16 ha = __float2bfloat16(a);
    __nv_bfloat16 hb = __float2bfloat16(b);
    __nv_bfloat162 hh; hh.x = ha; hh.y = hb;
    __nv_bfloat162 ll;
    ll.x = __float2bfloat16(a - __bfloat162float(ha));
    ll.y = __float2bfloat16(b - __bfloat162float(hb));
    hp = *(unsigned*)&hh;
    lp = *(unsigned*)&ll;
}

// ---------------------------------------------------------------------------
// cp.async helpers
// ---------------------------------------------------------------------------
__device__ __forceinline__ void cpa16(unsigned dst, const void* src)
{
    asm volatile("cp.async.ca.shared.global [%0], [%1], 16;"
                 :: "r"(dst), "l"(src));
}
__device__ __forceinline__ void cpa_commit()
{
    asm volatile("cp.async.commit_group;");
}

// ---------------------------------------------------------------------------
// mma.sync / ldmatrix (baseline sm_80 PTX — compiles under sm_103 target)
// ---------------------------------------------------------------------------
__device__ __forceinline__ void ldsm4(unsigned* r, unsigned addr)
{
    asm volatile("ldmatrix.sync.aligned.m8n8.x4.shared.b16 {%0,%1,%2,%3}, [%4];"
                 : "=r"(r[0]), "=r"(r[1]), "=r"(r[2]), "=r"(r[3]) : "r"(addr));
}
__device__ __forceinline__ void mma16816(float* d, const unsigned* a,
                                         unsigned b0, unsigned b1)
{
    asm volatile(
        "mma.sync.aligned.m16n8k16.row.col.f32.bf16.bf16.f32 "
        "{%0,%1,%2,%3}, {%4,%5,%6,%7}, {%8,%9}, {%0,%1,%2,%3};"
        : "+f"(d[0]), "+f"(d[1]), "+f"(d[2]), "+f"(d[3])
        : "r"(a[0]), "r"(a[1]), "r"(a[2]), "r"(a[3]), "r"(b0), "r"(b1));
}

// ---------------------------------------------------------------------------
// Prepass kernels
// ---------------------------------------------------------------------------
__global__ void bias_gather(const float* __restrict__ tcv,
                            const float* __restrict__ tsv,
                            const float* __restrict__ tch,
                            const float* __restrict__ tsh,
                            const int*   __restrict__ rel_idx)
{
    const int tbl = blockIdx.y;
    const int h   = blockIdx.z;
    const float* T = (tbl == 0) ? tcv : (tbl == 1) ? tsv : (tbl == 2) ? tch : tsh;
    int idx = blockIdx.x * 256 + threadIdx.x;      // idx = i*64 + j
    g_bias[(size_t)(tbl * NHEADS + h) * (NTOK * NTOK) + idx] =
        T[rel_idx[idx] * NHEADS + h];
}

__global__ __launch_bounds__(256)
void convert_split(const float* __restrict__ X,
                   __nv_bfloat16* __restrict__ hi,
                   __nv_bfloat16* __restrict__ lo, size_t n)
{
    size_t idx = ((size_t)blockIdx.x * 256 + threadIdx.x) * 4;
    if (idx >= n) return;
    float4 v = *(const float4*)(X + idx);
    float xs[4] = {v.x, v.y, v.z, v.w};
    __nv_bfloat16 h4[4], l4[4];
    #pragma unroll
    for (int c = 0; c < 4; c++) {
        __nv_bfloat16 hb = __float2bfloat16(xs[c]);
        h4[c] = hb;
        l4[c] = __float2bfloat16(xs[c] - __bfloat162float(hb));
    }
    *(ulonglong1*)(hi + idx) = *(ulonglong1*)h4;
    *(ulonglong1*)(lo + idx) = *(ulonglong1*)l4;
}

// ---------------------------------------------------------------------------
// Stage-1 tensor GEMM (HMMA): Y = X @ W^T + b, bf16 2-term compensated.
// Grid (2048, 1, 2): each CTA computes a FULL 128x384 row block.
//   - A loaded once as fp32 and split to bf16 hi/lo during the smem fill
//     (prepass X converts eliminated; A re-reads across n-blocks eliminated)
//   - W hi/lo for all 384 rows resident in smem (cp.async; L2-resident source)
// K = 96, pitch 104 halves (conflict-free ldmatrix). Y written fp32 row-major.
// ---------------------------------------------------------------------------
#define PB 104
#define S1_AH 0
#define S1_AL (128 * PB)                      // halves
#define S1_BH (2 * 128 * PB)
#define S1_BL (S1_BH + K4 * PB)
#define S1_HALVES (S1_BL + K4 * PB)           // 106496 halves
#define S1_SMEM (S1_HALVES * 2)               // 212992 B

__global__ __launch_bounds__(256)
void mma_gemm(const float* __restrict__ Xs, const float* __restrict__ Xe,
              const __nv_bfloat16* __restrict__ WsH,
              const __nv_bfloat16* __restrict__ WsL,
              const __nv_bfloat16* __restrict__ WeH,
              const __nv_bfloat16* __restrict__ WeL,
              const float* __restrict__ bs, const float* __restrict__ be)
{
    extern __shared__ __nv_bfloat16 smh[];
    const unsigned sb = (unsigned)__cvta_generic_to_shared(smh);

    const int t    = threadIdx.x;
    const int lane = t & 31;
    const int wid  = t >> 5;
    const int mBase = blockIdx.x * 128;
    const int z     = blockIdx.z;

    const float* X = z ? Xe : Xs;
    const __nv_bfloat16* Bh = z ? WeH : WsH;
    const __nv_bfloat16* Bl = z ? WeL : WsL;
    const float* bias = z ? be : bs;
    float* Y = z ? g_Ye : g_Ys;

    // ---- B fill via cp.async: 2 matrices x 384 rows x 12 granules(16B) ----
    #pragma unroll
    for (int it = 0; it < 18; it++) {
        int g   = t + 256 * it;               // 0..4607
        int row = g / 12;
        int gr  = g % 12;
        cpa16(sb + (S1_BH + row * PB) * 2 + gr * 16, Bh + row * CDIM + gr * 8);
        cpa16(sb + (S1_BL + row * PB) * 2 + gr * 16, Bl + row * CDIM + gr * 8);
    }
    cpa_commit();

    // ---- A fill: fp32 LDG.128 + split to hi/lo (3072 float4 granules) ----
    #pragma unroll
    for (int it = 0; it < 12; it++) {
        int g   = t + 256 * it;               // 0..3071
        int row = g / 24;
        int c4  = (g % 24) * 4;
        float4 v = *(const float4*)&X[(size_t)(mBase + row) * CDIM + c4];
        unsigned h0, l0, h1, l1;
        split2(v.x, v.y, h0, l0);
        split2(v.z, v.w, h1, l1);
        uint2 hh; hh.x = h0; hh.y = h1;
        uint2 ll; ll.x = l0; ll.y = l1;
        *(uint2*)&smh[S1_AH + row * PB + c4] = hh;
        *(uint2*)&smh[S1_AL + row * PB + c4] = ll;
    }
    asm volatile("cp.async.wait_group 0;");
    __syncthreads();

    const int mW = (wid & 3) * 32;
    const int nWb = (wid >> 2) * 64;          // 0 or 64 within each n-block

    const unsigned frow = (unsigned)(lane & 15);
    const unsigned fkof = (unsigned)(lane >> 4) * 8;

    for (int nb = 0; nb < 3; nb++) {
        const int nBase = nb * 128;

        float D[16][4];
        #pragma unroll
        for (int i = 0; i < 16; i++)
            #pragma unroll
            for (int j = 0; j < 4; j++) D[i][j] = 0.f;

        #pragma unroll
        for (int s = 0; s < 6; s++) {
            const unsigned k0 = s * 16;
            unsigned ah[2][4], al[2][4];
            #pragma unroll
            for (int m = 0; m < 2; m++) {
                unsigned off = ((mW + m * 16 + frow) * PB + k0 + fkof) * 2;
                ldsm4(ah[m], sb + (S1_AH * 2) + off);
                ldsm4(al[m], sb + (S1_AL * 2) + off);
            }
            #pragma unroll
            for (int p = 0; p < 4; p++) {
                unsigned boff = ((nBase + nWb + p * 16 + frow) * PB + k0 + fkof) * 2;
                unsigned bh[4], bl[4];
                ldsm4(bh, sb + (S1_BH * 2) + boff);
                ldsm4(bl, sb + (S1_BL * 2) + boff);
                #pragma unroll
                for (int m = 0; m < 2; m++) {
                    #pragma unroll
                    for (int na = 0; na < 2; na++) {
                        float* d = D[m * 8 + p * 2 + na];
                        mma16816(d, ah[m], bh[na], bh[na + 2]);
                        mma16816(d, ah[m], bl[na], bl[na + 2]);
                        mma16816(d, al[m], bh[na], bh[na + 2]);
                    }
                }
            }
        }

        // ---- epilogue for this n-block: bias + float2 stores, fp32 Y ----
        #pragma unroll
        for (int m = 0; m < 2; m++) {
            int rA = mBase + mW + m * 16 + (lane >> 2);
            #pragma unroll
            for (int n = 0; n < 8; n++) {
                int col = nBase + nWb + n * 8 + (lane & 3) * 2;
                float2 bv = *(const float2*)&bias[col];
                float* d = D[m * 8 + n];
                float2 r0; r0.x = d[0] + bv.x; r0.y = d[1] + bv.y;
                float2 r1; r1.x = d[2] + bv.x; r1.y = d[3] + bv.y;
                *(float2*)&Y[(size_t)rA * K4 + col]       = r0;
                *(float2*)&Y[(size_t)(rA + 8) * K4 + col] = r1;
            }
        }
    }
}

// ---------------------------------------------------------------------------
// Window attention on HMMA (R15 configuration — measured 1221 us total).
// Grid (BATCH, NHEADS, 2); block 256 (8 warps).
// warps 0-3 = type A (16 query rows each), warps 4-7 = type B.
// smem: Q/K pitch 40 halves, V stored transposed [d][j] pitch 72.
// ---------------------------------------------------------------------------
#define PQ  40
#define PV2 72
#define O_KH  0
#define O_KL  2560
#define O_QAH 5120
#define O_QAL 7680
#define O_QBH 10240
#define O_QBL 12800
#define O_VH  15360
#define O_VL  17664
#define ATT_HALVES 19968                      // 39936 B

__global__ __launch_bounds__(256)
void attn_mma()
{
    __shared__ __nv_bfloat16 smh[ATT_HALVES];
    const unsigned sb = (unsigned)__cvta_generic_to_shared(smh);

    const int b = blockIdx.x;
    const int h = blockIdx.y;
    const int z = blockIdx.z;
    const float* __restrict__ Y = z ? g_Ye : g_Ys;

    const int t    = threadIdx.x;
    const int lane = t & 31;
    const int wid  = t >> 5;

    // ---- load + convert: Q/K direct, V transposed ----
    {
        const int offs[3] = {0, 2 * CDIM, 3 * CDIM};     // k, qA, qB
        const int dh[3]   = {O_KH, O_QAH, O_QBH};
        #pragma unroll
        for (int tt = 0; tt < 3; tt++) {
            #pragma unroll
            for (int rr = 0; rr < 8; rr++) {
                int row = wid * 8 + rr;
                float f = Y[(size_t)(b * NTOK + row) * K4 + offs[tt] + h * HD + lane];
                __nv_bfloat16 hh = __float2bfloat16(f);
                __nv_bfloat16 ll = __float2bfloat16(f - __bfloat162float(hh));
                smh[dh[tt] + row * PQ + lane]        = hh;
                smh[dh[tt] + 2560 + row * PQ + lane] = ll;
            }
        }
        #pragma unroll
        for (int rr = 0; rr < 8; rr++) {
            int j = wid * 8 + rr;
            float f = Y[(size_t)(b * NTOK + j) * K4 + CDIM + h * HD + lane];
            __nv_bfloat16 hh = __float2bfloat16(f);
            __nv_bfloat16 ll = __float2bfloat16(f - __bfloat162float(hh));
            smh[O_VH + lane * PV2 + j] = hh;
            smh[O_VL + lane * PV2 + j] = ll;
        }
    }
    __syncthreads();

    const int type    = wid >> 2;
    const int rowBase = (wid & 3) * 16;
    const float scl   = type ? (z ? SCALE : SCALE * SCALE)
                             : (z ? 1.0f  : SCALE);
    const int  tbl    = type ? (z ? 2 : 3) : (z ? 1 : 0);
    const float* bias = g_bias + (size_t)(tbl * NHEADS + h) * (NTOK * NTOK);

    const unsigned frow = (unsigned)(lane & 15);
    const unsigned fkof = (unsigned)(lane >> 4) * 8;
    const int g = lane >> 2;
    const int q = lane & 3;

    // ---- Q fragments (hi/lo, 2 k-steps) ----
    const unsigned qbase = type ? O_QBH : O_QAH;
    unsigned qh[2][4], ql[2][4];
    #pragma unroll
    for (int ks = 0; ks < 2; ks++) {
        unsigned a = sb + (qbase + (rowBase + frow) * PQ + ks * 16 + fkof) * 2;
        ldsm4(qh[ks], a);
        ldsm4(ql[ks], a + 2560 * 2);
    }

    // ---- QK^T: D[8 n-tiles][4] ----
    float D[8][4];
    #pragma unroll
    for (int i = 0; i < 8; i++)
        #pragma unroll
        for (int j = 0; j < 4; j++) D[i][j] = 0.f;

    #pragma unroll
    for (int ng = 0; ng < 4; ng++) {
        unsigned kh[2][4], kl[2][4];
        #pragma unroll
        for (int ks = 0; ks < 2; ks++) {
            unsigned a = sb + (O_KH + (ng * 16 + frow) * PQ + ks * 16 + fkof) * 2;
            ldsm4(kh[ks], a);
            ldsm4(kl[ks], a + 2560 * 2);
        }
        #pragma unroll
        for (int ks = 0; ks < 2; ks++) {
            #pragma unroll
            for (int na = 0; na < 2; na++) {
                float* d = D[2 * ng + na];
                mma16816(d, qh[ks], kh[ks][na], kh[ks][na + 2]);
                mma16816(d, qh[ks], kl[ks][na], kl[ks][na + 2]);
                mma16816(d, ql[ks], kh[ks][na], kh[ks][na + 2]);
            }
        }
    }

    // ---- scale + bias ----
    #pragma unroll
    for (int nt = 0; nt < 8; nt++) {
        float2 b0 = *(const float2*)&bias[(rowBase + g) * NTOK + nt * 8 + 2 * q];
        float2 b1 = *(const float2*)&bias[(rowBase + g + 8) * NTOK + nt * 8 + 2 * q];
        D[nt][0] = fmaf(scl, D[nt][0], b0.x);
        D[nt][1] = fmaf(scl, D[nt][1], b0.y);
        D[nt][2] = fmaf(scl, D[nt][2], b1.x);
        D[nt][3] = fmaf(scl, D[nt][3], b1.y);
    }

    // ---- row softmax (quad shuffles; rows g and g+8) ----
    float m0 = -1e30f, m1 = -1e30f;
    #pragma unroll
    for (int nt = 0; nt < 8; nt++) {
        m0 = fmaxf(m0, fmaxf(D[nt][0], D[nt][1]));
        m1 = fmaxf(m1, fmaxf(D[nt][2], D[nt][3]));
    }
    m0 = fmaxf(m0, __shfl_xor_sync(0xffffffffu, m0, 1));
    m0 = fmaxf(m0, __shfl_xor_sync(0xffffffffu, m0, 2));
    m1 = fmaxf(m1, __shfl_xor_sync(0xffffffffu, m1, 1));
    m1 = fmaxf(m1, __shfl_xor_sync(0xffffffffu, m1, 2));

    float s0 = 0.f, s1 = 0.f;
    #pragma unroll
    for (int nt = 0; nt < 8; nt++) {
        D[nt][0] = fast_exp(D[nt][0] - m0);
        D[nt][1] = fast_exp(D[nt][1] - m0);
        D[nt][2] = fast_exp(D[nt][2] - m1);
        D[nt][3] = fast_exp(D[nt][3] - m1);
        s0 += D[nt][0] + D[nt][1];
        s1 += D[nt][2] + D[nt][3];
    }
    s0 += __shfl_xor_sync(0xffffffffu, s0, 1);
    s0 += __shfl_xor_sync(0xffffffffu, s0, 2);
    s1 += __shfl_xor_sync(0xffffffffu, s1, 1);
    s1 += __shfl_xor_sync(0xffffffffu, s1, 2);
    const float i0 = 1.f / s0;
    const float i1 = 1.f / s1;

    // ---- P fragments (hi/lo) from D registers; inv folded in ----
    unsigned pah[4][4], pal[4][4];
    #pragma unroll
    for (int kt = 0; kt < 4; kt++) {
        #pragma unroll
        for (int half = 0; half < 2; half++) {       // n-tile 2kt, 2kt+1
            float c0 = D[2 * kt + half][0] * i0;
            float c1 = D[2 * kt + half][1] * i0;
            float c2 = D[2 * kt + half][2] * i1;
            float c3 = D[2 * kt + half][3] * i1;
            split2(c0, c1, pah[kt][2 * half + 0], pal[kt][2 * half + 0]);
            split2(c2, c3, pah[kt][2 * half + 1], pal[kt][2 * half + 1]);
        }
    }

    // ---- PV: O[4 n-tiles][4] over n=32 dims, k=64 ----
    float O[4][4];
    #pragma unroll
    for (int i = 0; i < 4; i++)
        #pragma unroll
        for (int j = 0; j < 4; j++) O[i][j] = 0.f;

    #pragma unroll
    for (int nv = 0; nv < 2; nv++) {
        #pragma unroll
        for (int kt = 0; kt < 4; kt++) {
            unsigned a = sb + (O_VH + (nv * 16 + frow) * PV2 + kt * 16 + fkof) * 2;
            unsigned vh[4], vl[4];
            ldsm4(vh, a);
            ldsm4(vl, a + (O_VL - O_VH) * 2);
            #pragma unroll
            for (int na = 0; na < 2; na++) {
                float* d = O[2 * nv + na];
                mma16816(d, pah[kt], vh[na], vh[na + 2]);
                mma16816(d, pah[kt], vl[na], vl[na + 2]);
                mma16816(d, pal[kt], vh[na], vh[na + 2]);
            }
        }
    }

    // ---- epilogue: bf16 hi/lo row-major stores into merge buffers ----
    __nv_bfloat16* oHi = type ? g_Mh_hi : g_Mv_hi;
    __nv_bfloat16* oLo = type ? g_Mh_lo : g_Mv_lo;
    const int colb = (type ? (z ? 0 : CDIM) : (z ? CDIM : 0)) + h * HD;

    #pragma unroll
    for (int nt = 0; nt < 4; nt++) {
        int col = colb + nt * 8 + 2 * q;
        #pragma unroll
        for (int half = 0; half < 2; half++) {
            int row = b * NTOK + rowBase + g + 8 * half;
            unsigned hp, lp;
            split2(O[nt][2 * half + 0], O[nt][2 * half + 1], hp, lp);
            *(unsigned*)&oHi[(size_t)row * (2 * CDIM) + col] = hp;
            *(unsigned*)&oLo[(size_t)row * (2 * CDIM) + col] = lp;
        }
    }
}

// ---------------------------------------------------------------------------
// Stage-3 tensor GEMM (HMMA): C[M,96] = M[token,192] @ W[96,192]^T + bias.
// ---------------------------------------------------------------------------
#define PB2   200
#define AROW2 (PB2 * 2)
#define S3_AH 0
#define S3_AL (128 * AROW2)
#define S3_BH (2 * 128 * AROW2)
#define S3_BL (S3_BH + CDIM * AROW2)
#define S3_SMEM (S3_BL + CDIM * AROW2)

__global__ __launch_bounds__(256)
void mma_gemm3(const float* __restrict__ bpv, const float* __restrict__ bph,
               float* __restrict__ out, float* __restrict__ state)
{
    extern __shared__ char smc[];
    const unsigned sb = (unsigned)__cvta_generic_to_shared(smc);

    const int t    = threadIdx.x;
    const int lane = t & 31;
    const int wid  = t >> 5;
    const int mBase = blockIdx.x * 128;
    const int z     = blockIdx.z;

    const __nv_bfloat16* Ah = z ? g_Mh_hi : g_Mv_hi;
    const __nv_bfloat16* Al = z ? g_Mh_lo : g_Mv_lo;
    const __nv_bfloat16* Bh = z ? g_Wph_hi : g_Wpv_hi;
    const __nv_bfloat16* Bl = z ? g_Wph_lo : g_Wpv_lo;
    const float* bias = z ? bph : bpv;
    float* C = z ? state : out;

    {
        const __nv_bfloat16* aH = Ah + (size_t)mBase * (2 * CDIM);
        const __nv_bfloat16* aL = Al + (size_t)mBase * (2 * CDIM);
        #pragma unroll
        for (int it = 0; it < 12; it++) {
            int g   = t + 256 * it;
            int row = g / 24;
            int gr  = g % 24;
            cpa16(sb + S3_AH + row * AROW2 + gr * 16, aH + row * (2 * CDIM) + gr * 8);
            cpa16(sb + S3_AL + row * AROW2 + gr * 16, aL + row * (2 * CDIM) + gr * 8);
        }
        #pragma unroll
        for (int it = 0; it < 9; it++) {
            int g = t + 256 * it;
            int row = g / 24;
            int gr  = g % 24;
            cpa16(sb + S3_BH + row * AROW2 + gr * 16, Bh + row * (2 * CDIM) + gr * 8);
            cpa16(sb + S3_BL + row * AROW2 + gr * 16, Bl + row * (2 * CDIM) + gr * 8);
        }
        cpa_commit();
        asm volatile("cp.async.wait_group 0;");
    }
    __syncthreads();

    const int mW = (wid & 3) * 32;
    const int nW = (wid >> 2) * 48;

    float D[12][4];
    #pragma unroll
    for (int i = 0; i < 12; i++)
        #pragma unroll
        for (int j = 0; j < 4; j++) D[i][j] = 0.f;

    const unsigned frow = (unsigned)(lane & 15);
    const unsigned fkof = (unsigned)(lane >> 4) * 8;

    #pragma unroll
    for (int s = 0; s < 12; s++) {
        const unsigned k0 = s * 16;
        unsigned ah[2][4], al[2][4];
        #pragma unroll
        for (int m = 0; m < 2; m++) {
            unsigned off = ((mW + m * 16 + frow) * PB2 + k0 + fkof) * 2;
            ldsm4(ah[m], sb + S3_AH + off);
            ldsm4(al[m], sb + S3_AL + off);
        }
        #pragma unroll
        for (int p = 0; p < 3; p++) {
            unsigned boff = ((nW + p * 16 + frow) * PB2 + k0 + fkof) * 2;
            unsigned bh[4], bl[4];
            ldsm4(bh, sb + S3_BH + boff);
            ldsm4(bl, sb + S3_BL + boff);
            #pragma unroll
            for (int m = 0; m < 2; m++) {
                #pragma unroll
                for (int na = 0; na < 2; na++) {
                    float* d = D[m * 6 + p * 2 + na];
                    mma16816(d, ah[m], bh[na], bh[na + 2]);
                    mma16816(d, ah[m], bl[na], bl[na + 2]);
                    mma16816(d, al[m], bh[na], bh[na + 2]);
                }
            }
        }
    }

    #pragma unroll
    for (int m = 0; m < 2; m++) {
        int rA = mBase + mW + m * 16 + (lane >> 2);
        #pragma unroll
        for (int n = 0; n < 6; n++) {
            int col = nW + n * 8 + (lane & 3) * 2;
            float2 bv = *(const float2*)&bias[col];
            float* d = D[m * 6 + n];
            float2 r0; r0.x = d[0] + bv.x; r0.y = d[1] + bv.y;
            float2 r1; r1.x = d[2] + bv.x; r1.y = d[3] + bv.y;
            *(float2*)&C[(size_t)rA * CDIM + col]       = r0;
            *(float2*)&C[(size_t)(rA + 8) * CDIM + col] = r1;
        }
    }
}

// ---------------------------------------------------------------------------
// Launch
// ---------------------------------------------------------------------------
extern "C" void kernel_launch(void* const* d_in, const int* in_sizes, int n_in,
                              void* d_out, int out_size)
{
    const float* input_x = (const float*)d_in[0];
    const float* state_x = (const float*)d_in[1];
    const float* Ws      = (const float*)d_in[2];
    const float* bs      = (const float*)d_in[3];
    const float* We      = (const float*)d_in[4];
    const float* be      = (const float*)d_in[5];
    const float* tcv     = (const float*)d_in[6];
    const float* tsv     = (const float*)d_in[7];
    const float* tch     = (const float*)d_in[8];
    const float* tsh     = (const float*)d_in[9];
    const float* Wpv     = (const float*)d_in[10];
    const float* bpv     = (const float*)d_in[11];
    const float* Wph     = (const float*)d_in[12];
    const float* bph     = (const float*)d_in[13];
    const int*   rel_idx = (const int*)d_in[14];

    float* out   = (float*)d_out;
    float* state = out + (size_t)MTOK * CDIM;

    __nv_bfloat16 *pWsH, *pWsL, *pWeH, *pWeL;
    __nv_bfloat16 *pWpvH, *pWpvL, *pWphH, *pWphL;
    cudaGetSymbolAddress((void**)&pWsH, g_Ws_hi);
    cudaGetSymbolAddress((void**)&pWsL, g_Ws_lo);
    cudaGetSymbolAddress((void**)&pWeH, g_We_hi);
    cudaGetSymbolAddress((void**)&pWeL, g_We_lo);
    cudaGetSymbolAddress((void**)&pWpvH, g_Wpv_hi);
    cudaGetSymbolAddress((void**)&pWpvL, g_Wpv_lo);
    cudaGetSymbolAddress((void**)&pWphH, g_Wph_hi);
    cudaGetSymbolAddress((void**)&pWphL, g_Wph_lo);

    cudaFuncSetAttribute(mma_gemm,
                         cudaFuncAttributeMaxDynamicSharedMemorySize, S1_SMEM);
    cudaFuncSetAttribute(mma_gemm3,
                         cudaFuncAttributeMaxDynamicSharedMemorySize, S3_SMEM);

    // Prepass: W converts + bias gather (X converts eliminated)
    {
        size_t nW = (size_t)K4 * CDIM;
        convert_split<<<(unsigned)((nW / 4 + 255) / 256), 256>>>(Ws, pWsH, pWsL, nW);
        convert_split<<<(unsigned)((nW / 4 + 255) / 256), 256>>>(We, pWeH, pWeL, nW);
        size_t nP = (size_t)CDIM * 2 * CDIM;
        convert_split<<<(unsigned)((nP / 4 + 255) / 256), 256>>>(Wpv, pWpvH, pWpvL, nP);
        convert_split<<<(unsigned)((nP / 4 + 255) / 256), 256>>>(Wph, pWphH, pWphL, nP);
        dim3 gb(NTOK * NTOK / 256, 4, NHEADS);
        bias_gather<<<gb, 256>>>(tcv, tsv, tch, tsh, rel_idx);
    }

    // Stage 1: projections on HMMA (full 384-col row blocks, in-kernel A split)
    {
        dim3 grid(MTOK / 128, 1, 2);
        mma_gemm<<<grid, 256, S1_SMEM>>>(state_x, input_x,
                                         pWsH, pWsL, pWeH, pWeL, bs, be);
    }

    // Stage 2: window attention on HMMA
    {
        dim3 grid(BATCH, NHEADS, 2);
        attn_mma<<<grid, 256>>>();
    }

    // Stage 3: output projections on HMMA
    {
        dim3 grid(MTOK / 128, 1, 2);
        mma_gemm3<<<grid, 256, S3_SMEM>>>(bpv, bph, out, state);
    }
}